// round 16
// baseline (speedup 1.0000x reference)
#include <cuda_runtime.h>
#include <cuda_fp16.h>
#include <cstdint>

#define HH 80
#define WW 80
#define HWSZ 6400
#define NB 2
#define CI 64
#define PH 86
#define PHW2 7396   // 86*86

// ---------------- scratch (__device__ globals; no allocation) ----------------
__device__ float g_off3[NB * 18 * HWSZ];
__device__ float g_mask3[NB * 9 * HWSZ];
__device__ float g_off5[NB * 50 * HWSZ];
__device__ float g_mask5[NB * 25 * HWSZ];
__device__ float g_off7[NB * 98 * HWSZ];
__device__ float g_mask7[NB * 49 * HWSZ];
// deform A: [t][kp=c/2][oc] half2-packed (c, c+1)
__device__ uint32_t g_wt2_3[9 * 32 * 64];
__device__ uint32_t g_wt2_5[25 * 32 * 64];
__device__ uint32_t g_wt2_7[49 * 32 * 64];
// conv A: [kp=(t,c)/2][ocpad] half2-packed
__device__ uint32_t g_wa2_3[288 * 32];
__device__ uint32_t g_wa2_5[800 * 96];
__device__ uint32_t g_wa2_7[1568 * 160];
// padded image, 8-channel interleaved half2: [b][cg=8][pix] (conv B staging)
__device__ uint4 g_xpad8[NB * 8 * PHW2];
// padded image, 4-channel interleaved fp32: [b][cq=16][pix] (deform gather)
__device__ float4 g_xpadf[NB * 16 * PHW2];

template <int K> __device__ __forceinline__ float* off_buf() {
    if constexpr (K == 3) return g_off3;
    else if constexpr (K == 5) return g_off5;
    else return g_off7;
}
template <int K> __device__ __forceinline__ float* mask_buf() {
    if constexpr (K == 3) return g_mask3;
    else if constexpr (K == 5) return g_mask5;
    else return g_mask7;
}
template <int K> __device__ __forceinline__ uint32_t* wt2_buf() {
    if constexpr (K == 3) return g_wt2_3;
    else if constexpr (K == 5) return g_wt2_5;
    else return g_wt2_7;
}
template <int K> __device__ __forceinline__ uint32_t* wa2_buf() {
    if constexpr (K == 3) return g_wa2_3;
    else if constexpr (K == 5) return g_wa2_5;
    else return g_wa2_7;
}

__device__ __forceinline__ uint32_t packh2(float a, float b) {
    __half2 h = __floats2half2_rn(a, b);
    return *reinterpret_cast<uint32_t*>(&h);
}

__device__ __forceinline__ void mma16(float c[4], uint32_t a0, uint32_t a1,
                                      uint32_t a2, uint32_t a3,
                                      uint32_t b0, uint32_t b1) {
    asm volatile(
        "mma.sync.aligned.m16n8k16.row.col.f32.f16.f16.f32 "
        "{%0,%1,%2,%3},{%4,%5,%6,%7},{%8,%9},{%0,%1,%2,%3};"
        : "+f"(c[0]), "+f"(c[1]), "+f"(c[2]), "+f"(c[3])
        : "r"(a0), "r"(a1), "r"(a2), "r"(a3), "r"(b0), "r"(b1));
}

// slot within a k16 block for local k-pair j (0..7): frag wants kp=tg at 2tg,
// kp=tg+4 at 2tg+1 so (b0,b1) is one 8-byte load.
__device__ __forceinline__ int slot8(int j) { return (j & 3) * 2 + (j >> 2); }

// ---------------- prep: pack weights + padded images ----------------
#define S_WT2 (83 * 2048)                 // (9+25+49)*32*64
#define S_WA2 (288 * 32 + 800 * 96 + 1568 * 160)
#define S_XP8 (NB * 8 * PHW2)
#define S_XPF (NB * 16 * PHW2)
__global__ __launch_bounds__(256) void prep_all(
    const float* __restrict__ x,
    const float* __restrict__ wd3, const float* __restrict__ wd5,
    const float* __restrict__ wd7,
    const float* __restrict__ wo3, const float* __restrict__ wm3,
    const float* __restrict__ wo5, const float* __restrict__ wm5,
    const float* __restrict__ wo7, const float* __restrict__ wm7) {
    int idx = blockIdx.x * 256 + threadIdx.x;
    if (idx < S_WT2) {
        const float* w; uint32_t* dst; int kk;
        if (idx < 9 * 2048) { w = wd3; dst = g_wt2_3; kk = 9; }
        else if (idx < 34 * 2048) { idx -= 9 * 2048; w = wd5; dst = g_wt2_5; kk = 25; }
        else { idx -= 34 * 2048; w = wd7; dst = g_wt2_7; kk = 49; }
        int oc = idx & 63;
        int kp = (idx >> 6) & 31;
        int t = idx >> 11;
        int c = kp * 2;
        dst[idx] = packh2(w[(oc * 64 + c) * kk + t], w[(oc * 64 + c + 1) * kk + t]);
        return;
    }
    idx -= S_WT2;
    if (idx < S_WA2) {
        const float* wo; const float* wm; uint32_t* dst; int kk, ocw;
        if (idx < 288 * 32) { wo = wo3; wm = wm3; dst = g_wa2_3; kk = 9; ocw = 32; }
        else if (idx < 288 * 32 + 800 * 96) {
            idx -= 288 * 32; wo = wo5; wm = wm5; dst = g_wa2_5; kk = 25; ocw = 96;
        } else {
            idx -= 288 * 32 + 800 * 96; wo = wo7; wm = wm7; dst = g_wa2_7; kk = 49; ocw = 160;
        }
        int oc = idx % ocw;
        int kpg = idx / ocw;
        int t = kpg >> 5;
        int c = (kpg & 31) * 2;
        float va = 0.f, vb = 0.f;
        if (oc < 2 * kk) {
            va = wo[(oc * 64 + c) * kk + t];
            vb = wo[(oc * 64 + c + 1) * kk + t];
        } else if (oc < 3 * kk) {
            va = wm[((oc - 2 * kk) * 64 + c) * kk + t];
            vb = wm[((oc - 2 * kk) * 64 + c + 1) * kk + t];
        }
        dst[idx] = packh2(va, vb);
        return;
    }
    idx -= S_WA2;
    if (idx < S_XP8) {
        int pix = idx % PHW2;
        int rest = idx / PHW2;
        int cg = rest & 7;
        int b = rest >> 3;
        int yp = pix / PH - 3;
        int xp = pix % PH - 3;
        uint4 v = make_uint4(0u, 0u, 0u, 0u);
        if (yp >= 0 && yp < HH && xp >= 0 && xp < WW) {
            const float* xs = x + (b * 64 + cg * 8) * HWSZ + yp * WW + xp;
            v.x = packh2(__ldg(xs), __ldg(xs + HWSZ));
            v.y = packh2(__ldg(xs + 2 * HWSZ), __ldg(xs + 3 * HWSZ));
            v.z = packh2(__ldg(xs + 4 * HWSZ), __ldg(xs + 5 * HWSZ));
            v.w = packh2(__ldg(xs + 6 * HWSZ), __ldg(xs + 7 * HWSZ));
        }
        g_xpad8[idx] = v;
        return;
    }
    idx -= S_XP8;
    if (idx < S_XPF) {
        int pix = idx % PHW2;
        int rest = idx / PHW2;
        int cq = rest & 15;
        int b = rest >> 4;
        int yp = pix / PH - 3;
        int xp = pix % PH - 3;
        float4 v = make_float4(0.f, 0.f, 0.f, 0.f);
        if (yp >= 0 && yp < HH && xp >= 0 && xp < WW) {
            const float* xs = x + (b * 64 + cq * 4) * HWSZ + yp * WW + xp;
            v.x = __ldg(xs);
            v.y = __ldg(xs + HWSZ);
            v.z = __ldg(xs + 2 * HWSZ);
            v.w = __ldg(xs + 3 * HWSZ);
        }
        g_xpadf[idx] = v;
    }
}

// ---------------- conv phase: G oc-groups x 128 pix per CTA, fp16 MMA --------
// Tap-sized chunks (32 kp = one tap), depth-1 register pipeline; B staged with
// 4x LDG.128 from the 8-channel-interleaved image. (R15, best measured.)
template <int K, int G, int OCW, int OCB>
__device__ __forceinline__ void conv_branch(
    const float* __restrict__ b_off, const float* __restrict__ b_mask,
    uint32_t* smem, int b, int pbase) {
    constexpr int KK = K * K;
    constexpr int P = K / 2;
    constexpr int NCH = KK;              // one chunk per tap
    constexpr int MST = G * 32 + 8;      // u32 stride, mod 32 == 8
    constexpr int BST = 40;              // 32 kp + pad, mod 32 == 8

    uint32_t* As = smem;                 // 2 * 32 * MST
    uint32_t* Bs = smem + 2 * 32 * MST;  // 2 * 128 * BST

    const int tid = threadIdx.x;
    const int wid = tid >> 5;
    const int lane = tid & 31;
    const int g = lane >> 2;
    const int tg = lane & 3;
    const int mbase = (wid & 1) * 16;
    const int nbase = (wid >> 1) * 32;

    // staging ids
    const int akp = tid >> 3;            // A: kp row 0..31
    const int ao4 = (tid & 7) * 4;       // A: 4 u32 (4 oc)
    const int bpix = tid & 127;          // B: pixel
    const int blk = tid >> 7;            // B: channel half (4 cgroups)
    const int phw = pbase + bpix;
    const int ph = phw / WW;
    const int pw = phw - ph * WW;
    const int pbase86 = (ph + 3 - P) * PH + (pw + 3 - P);
    const uint4* xp8blk = g_xpad8 + (b * 8 + blk * 4) * PHW2;
    const uint32_t* wa = wa2_buf<K>();

    uint4 aR[G];
    uint32_t bR[16];

    auto ldgAB = [&](int t) {
#pragma unroll
        for (int gi = 0; gi < G; ++gi)
            aR[gi] = *(const uint4*)(wa + (t * 32 + akp) * OCW + OCB + gi * 32 + ao4);
        const int ky = t / K;
        const int kx = t - ky * K;
        const uint4* src = xp8blk + pbase86 + ky * PH + kx;
#pragma unroll
        for (int c = 0; c < 4; ++c) {
            uint4 v = __ldg(src + c * PHW2);
            bR[c * 4 + 0] = v.x;
            bR[c * 4 + 1] = v.y;
            bR[c * 4 + 2] = v.z;
            bR[c * 4 + 3] = v.w;
        }
    };
    auto stsAB = [&](int buf) {
        uint32_t* Ab = As + buf * 32 * MST;
        uint32_t* Bb = Bs + buf * 128 * BST;
#pragma unroll
        for (int gi = 0; gi < G; ++gi)
            *(uint4*)(Ab + akp * MST + gi * 32 + ao4) = aR[gi];
        uint32_t h[16];
#pragma unroll
        for (int j = 0; j < 16; ++j)
            h[(j >> 3) * 8 + slot8(j & 7)] = bR[j];
        uint32_t* dst = Bb + bpix * BST + blk * 16;
        *(uint4*)(dst) = make_uint4(h[0], h[1], h[2], h[3]);
        *(uint4*)(dst + 4) = make_uint4(h[4], h[5], h[6], h[7]);
        *(uint4*)(dst + 8) = make_uint4(h[8], h[9], h[10], h[11]);
        *(uint4*)(dst + 12) = make_uint4(h[12], h[13], h[14], h[15]);
    };

    float acc[G][4][4];
#pragma unroll
    for (int gi = 0; gi < G; ++gi)
#pragma unroll
        for (int i = 0; i < 4; ++i)
#pragma unroll
            for (int l = 0; l < 4; ++l) acc[gi][i][l] = 0.f;

    ldgAB(0);
    for (int n = 0; n < NCH; ++n) {
        const int buf = n & 1;
        stsAB(buf);
        __syncthreads();
        const uint32_t* Ab = As + buf * 32 * MST;
        const uint32_t* Bb = Bs + buf * 128 * BST;
#pragma unroll
        for (int kb = 0; kb < 4; ++kb) {
            uint2 bb[4];
#pragma unroll
            for (int nt = 0; nt < 4; ++nt)
                bb[nt] = *(const uint2*)(Bb + (nbase + nt * 8 + g) * BST + kb * 8 + 2 * tg);
            const uint32_t* Ar = Ab + (kb * 8 + tg) * MST;
            const uint32_t* Ar4 = Ab + (kb * 8 + tg + 4) * MST;
#pragma unroll
            for (int gi = 0; gi < G; ++gi) {
                const int mb = gi * 32 + mbase + g;
                uint32_t a0 = Ar[mb];
                uint32_t a1 = Ar[mb + 8];
                uint32_t a2 = Ar4[mb];
                uint32_t a3 = Ar4[mb + 8];
#pragma unroll
                for (int nt = 0; nt < 4; ++nt)
                    mma16(acc[gi][nt], a0, a1, a2, a3, bb[nt].x, bb[nt].y);
            }
        }
        if (n + 1 < NCH) ldgAB(n + 1);
    }

    // epilogue
#pragma unroll
    for (int gi = 0; gi < G; ++gi)
#pragma unroll
        for (int r = 0; r < 2; ++r) {
            int ocl = OCB + gi * 32 + mbase + g + r * 8;
            float* dst;
            float bias;
            bool msk;
            if (ocl < 2 * KK) {
                dst = off_buf<K>() + ((size_t)(b * 2 * KK + ocl)) * HWSZ;
                bias = __ldg(b_off + ocl);
                msk = false;
            } else if (ocl < 3 * KK) {
                dst = mask_buf<K>() + ((size_t)(b * KK + (ocl - 2 * KK))) * HWSZ;
                bias = __ldg(b_mask + (ocl - 2 * KK));
                msk = true;
            } else continue;
#pragma unroll
            for (int nt = 0; nt < 4; ++nt) {
                int col = pbase + nbase + nt * 8 + tg * 2;
                float f0 = acc[gi][nt][r * 2] + bias;
                float f1 = acc[gi][nt][r * 2 + 1] + bias;
                if (msk) {
                    f0 = 1.f / (1.f + __expf(-f0));
                    f1 = 1.f / (1.f + __expf(-f1));
                }
                *(float2*)(dst + col) = make_float2(f0, f1);
            }
        }
}

// LPT cid order: 0-99 k7 G=3 | 100-199 k7 G=2 | 200-299 k5 | 300-399 k3
__global__ __launch_bounds__(256, 2) void conv_tc(
    const float* __restrict__ b_off3, const float* __restrict__ b_mask3,
    const float* __restrict__ b_off5, const float* __restrict__ b_mask5,
    const float* __restrict__ b_off7, const float* __restrict__ b_mask7) {
    extern __shared__ uint32_t dynsmem_c[];
    const int cid = blockIdx.x;
    const int j = cid % 100;
    const int b = j / 50;
    const int pbase = (j % 50) * 128;
    if (cid < 100)
        conv_branch<7, 3, 160, 0>(b_off7, b_mask7, dynsmem_c, b, pbase);
    else if (cid < 200)
        conv_branch<7, 2, 160, 96>(b_off7, b_mask7, dynsmem_c, b, pbase);
    else if (cid < 300)
        conv_branch<5, 3, 96, 0>(b_off5, b_mask5, dynsmem_c, b, pbase);
    else
        conv_branch<3, 1, 32, 0>(b_off3, b_mask3, dynsmem_c, b, pbase);
}

// ---------------- deform phase: 64 oc x 128 pix per CTA, fp16 MMA ------------
// Tap-sized chunks; gather reads the fp32 float4 image (zero F2F conversions),
// fp32 combine, one fp16 rounding at the end.
template <int K, int BROFF>
__device__ __forceinline__ void deform_branch(
    float* __restrict__ out, uint32_t* smem, int b, int pbase) {
    constexpr int KK = K * K;
    constexpr int P = K / 2;
    constexpr int NCH = KK;              // one chunk per tap
    constexpr int AST = 72;              // u32 stride, mod 32 == 8
    constexpr int BST = 40;              // 32 kp + pad, mod 32 == 8

    uint32_t* As = smem;                 // 2 * 32 * 72
    uint32_t* Bs = smem + 2 * 32 * AST;  // 2 * 128 * 40

    const int tid = threadIdx.x;
    const int wid = tid >> 5;
    const int lane = tid & 31;
    const int g = lane >> 2;
    const int tg = lane & 3;
    const int mbase = (wid & 1) * 32;    // 2 m-groups of 32
    const int nbase = (wid >> 1) * 32;   // 4 n-groups of 32

    // staging ids
    const int pix = tid & 127;
    const int blk = tid >> 7;            // channel half (8 quad-groups)
    const int akp = tid >> 4;            // A: kp rows akp and akp+16
    const int ao4 = (tid & 15) * 4;      // A: 4 u32 (4 oc)
    const int shw = pbase + pix;
    const int sh = shw / WW;
    const int swp = shw - sh * WW;
    const float4* xpfblk = g_xpadf + (b * 16 + blk * 8) * PHW2;
    const uint32_t* wt = wt2_buf<K>();
    const float* goff = off_buf<K>();
    const float* gmask = mask_buf<K>();

    float r_oy, r_ox, r_m;
    uint4 aR[2];
    uint32_t hR[16];

    auto prefetch_raw = [&](int t) {
        if (t < KK) {
            r_oy = __ldg(goff + (b * 2 * KK + 2 * t) * HWSZ + shw);
            r_ox = __ldg(goff + (b * 2 * KK + 2 * t + 1) * HWSZ + shw);
            r_m = __ldg(gmask + (b * KK + t) * HWSZ + shw);
        }
    };

    auto ldgAB = [&](int t) {
        aR[0] = *(const uint4*)(wt + (t * 32 + akp) * 64 + ao4);
        aR[1] = *(const uint4*)(wt + (t * 32 + akp + 16) * 64 + ao4);
        int ty = t / K, tx = t - ty * K;
        float py = (float)(sh - P + ty + 3) + r_oy;
        float px = (float)(swp - P + tx + 3) + r_ox;
        float y0f = floorf(py), x0f = floorf(px);
        float wy1 = py - y0f, wx1 = px - x0f;
        float wy0 = 1.f - wy1, wx0 = 1.f - wx1;
        int y0 = min(max((int)y0f, 0), PH - 1);
        int y1 = min(max((int)y0f + 1, 0), PH - 1);
        int x0 = min(max((int)x0f, 0), PH - 1);
        int x1 = min(max((int)x0f + 1, 0), PH - 1);
        float4 dw = make_float4(wy0 * wx0 * r_m, wy0 * wx1 * r_m,
                                wy1 * wx0 * r_m, wy1 * wx1 * r_m);
        int4 di = make_int4(y0 * PH + x0, y0 * PH + x1, y1 * PH + x0, y1 * PH + x1);
        prefetch_raw(t + 1);
#pragma unroll
        for (int cg = 0; cg < 8; ++cg) {
            const float4* gp = xpfblk + cg * PHW2;
            float4 s0 = __ldg(gp + di.x);
            float4 s1 = __ldg(gp + di.y);
            float4 s2 = __ldg(gp + di.z);
            float4 s3 = __ldg(gp + di.w);
            float va0 = dw.x * s0.x + dw.y * s1.x + dw.z * s2.x + dw.w * s3.x;
            float vb0 = dw.x * s0.y + dw.y * s1.y + dw.z * s2.y + dw.w * s3.y;
            float va1 = dw.x * s0.z + dw.y * s1.z + dw.z * s2.z + dw.w * s3.z;
            float vb1 = dw.x * s0.w + dw.y * s1.w + dw.z * s2.w + dw.w * s3.w;
            hR[cg * 2 + 0] = packh2(va0, vb0);
            hR[cg * 2 + 1] = packh2(va1, vb1);
        }
    };
    auto stsAB = [&](int buf) {
        uint32_t* Ab = As + buf * 32 * AST;
        uint32_t* Bb = Bs + buf * 128 * BST;
        *(uint4*)(Ab + akp * AST + ao4) = aR[0];
        *(uint4*)(Ab + (akp + 16) * AST + ao4) = aR[1];
        uint32_t h[16];
#pragma unroll
        for (int i = 0; i < 16; ++i)
            h[(i >> 3) * 8 + slot8(i & 7)] = hR[i];
        uint32_t* dst = Bb + pix * BST + blk * 16;
        *(uint4*)(dst) = make_uint4(h[0], h[1], h[2], h[3]);
        *(uint4*)(dst + 4) = make_uint4(h[4], h[5], h[6], h[7]);
        *(uint4*)(dst + 8) = make_uint4(h[8], h[9], h[10], h[11]);
        *(uint4*)(dst + 12) = make_uint4(h[12], h[13], h[14], h[15]);
    };

    float acc[2][4][4];
#pragma unroll
    for (int mt = 0; mt < 2; ++mt)
#pragma unroll
        for (int i = 0; i < 4; ++i)
#pragma unroll
            for (int l = 0; l < 4; ++l) acc[mt][i][l] = 0.f;

    prefetch_raw(0);
    ldgAB(0);
    for (int n = 0; n < NCH; ++n) {
        const int buf = n & 1;
        stsAB(buf);
        __syncthreads();
        const uint32_t* Ab = As + buf * 32 * AST;
        const uint32_t* Bb = Bs + buf * 128 * BST;
#pragma unroll
        for (int kb = 0; kb < 4; ++kb) {
            uint2 bb[4];
#pragma unroll
            for (int nt = 0; nt < 4; ++nt)
                bb[nt] = *(const uint2*)(Bb + (nbase + nt * 8 + g) * BST + kb * 8 + 2 * tg);
            const uint32_t* Ar = Ab + (kb * 8 + tg) * AST;
            const uint32_t* Ar4 = Ab + (kb * 8 + tg + 4) * AST;
#pragma unroll
            for (int mt = 0; mt < 2; ++mt) {
                const int mb = mbase + mt * 16 + g;
                uint32_t a0 = Ar[mb];
                uint32_t a1 = Ar[mb + 8];
                uint32_t a2 = Ar4[mb];
                uint32_t a3 = Ar4[mb + 8];
#pragma unroll
                for (int nt = 0; nt < 4; ++nt)
                    mma16(acc[mt][nt], a0, a1, a2, a3, bb[nt].x, bb[nt].y);
            }
        }
        if (n + 1 < NCH) ldgAB(n + 1);
    }

#pragma unroll
    for (int mt = 0; mt < 2; ++mt)
#pragma unroll
        for (int r = 0; r < 2; ++r) {
            int ocl = BROFF + mbase + mt * 16 + g + r * 8;
            float* dst = out + ((size_t)(b * 192 + ocl)) * HWSZ;
#pragma unroll
            for (int nt = 0; nt < 4; ++nt) {
                int col = pbase + nbase + nt * 8 + tg * 2;
                *(float2*)(dst + col) =
                    make_float2(acc[mt][nt][r * 2], acc[mt][nt][r * 2 + 1]);
            }
        }
}

// LPT cid order: 0-99 k7 | 100-199 k5 | 200-299 k3
__global__ __launch_bounds__(256, 2) void deform_tc(float* __restrict__ out) {
    extern __shared__ uint32_t dynsmem_d[];
    const int cid = blockIdx.x;
    const int j = cid % 100;
    const int b = j / 50;
    const int pbase = (j % 50) * 128;
    if (cid < 100) deform_branch<7, 128>(out, dynsmem_d, b, pbase);
    else if (cid < 200) deform_branch<5, 64>(out, dynsmem_d, b, pbase);
    else deform_branch<3, 0>(out, dynsmem_d, b, pbase);
}

extern "C" void kernel_launch(void* const* d_in, const int* in_sizes, int n_in,
                              void* d_out, int out_size) {
    (void)in_sizes; (void)n_in; (void)out_size;
    const float* x       = (const float*)d_in[0];
    const float* w_off3  = (const float*)d_in[1];
    const float* b_off3  = (const float*)d_in[2];
    const float* w_mask3 = (const float*)d_in[3];
    const float* b_mask3 = (const float*)d_in[4];
    const float* w_dcn3  = (const float*)d_in[5];
    const float* w_off5  = (const float*)d_in[6];
    const float* b_off5  = (const float*)d_in[7];
    const float* w_mask5 = (const float*)d_in[8];
    const float* b_mask5 = (const float*)d_in[9];
    const float* w_dcn5  = (const float*)d_in[10];
    const float* w_off7  = (const float*)d_in[11];
    const float* b_off7  = (const float*)d_in[12];
    const float* w_mask7 = (const float*)d_in[13];
    const float* b_mask7 = (const float*)d_in[14];
    const float* w_dcn7  = (const float*)d_in[15];
    float* out = (float*)d_out;

    // conv: (2*32*104 + 2*128*40)*4 = 67584 B (G=3 worst case)
    // deform: (2*32*72 + 2*128*40)*4 = 59392 B
    const int conv_smem = (2 * 32 * 104 + 2 * 128 * 40) * 4;
    const int def_smem = (2 * 32 * 72 + 2 * 128 * 40) * 4;
    cudaFuncSetAttribute(conv_tc, cudaFuncAttributeMaxDynamicSharedMemorySize,
                         conv_smem);
    cudaFuncSetAttribute(deform_tc, cudaFuncAttributeMaxDynamicSharedMemorySize,
                         def_smem);

    const int prep_total = S_WT2 + S_WA2 + S_XP8 + S_XPF;
    prep_all<<<(prep_total + 255) / 256, 256>>>(
        x, w_dcn3, w_dcn5, w_dcn7,
        w_off3, w_mask3, w_off5, w_mask5, w_off7, w_mask7);

    conv_tc<<<400, 256, conv_smem>>>(
        b_off3, b_mask3, b_off5, b_mask5, b_off7, b_mask7);

    deform_tc<<<300, 256, def_smem>>>(out);
}

// round 17
// speedup vs baseline: 1.5259x; 1.5259x over previous
#include <cuda_runtime.h>
#include <cuda_fp16.h>
#include <cstdint>

#define HH 80
#define WW 80
#define HWSZ 6400
#define NB 2
#define CI 64
#define PH 86
#define PHW2 7396   // 86*86

// ---------------- scratch (__device__ globals; no allocation) ----------------
__device__ float g_off3[NB * 18 * HWSZ];
__device__ float g_mask3[NB * 9 * HWSZ];
__device__ float g_off5[NB * 50 * HWSZ];
__device__ float g_mask5[NB * 25 * HWSZ];
__device__ float g_off7[NB * 98 * HWSZ];
__device__ float g_mask7[NB * 49 * HWSZ];
// deform A: [t][kp=c/2][oc] half2-packed (c, c+1)
__device__ uint32_t g_wt2_3[9 * 32 * 64];
__device__ uint32_t g_wt2_5[25 * 32 * 64];
__device__ uint32_t g_wt2_7[49 * 32 * 64];
// conv A: [kp=(t,c)/2][ocpad] half2-packed
__device__ uint32_t g_wa2_3[288 * 32];
__device__ uint32_t g_wa2_5[800 * 96];
__device__ uint32_t g_wa2_7[1568 * 160];
// padded image, 8-channel interleaved half2: [b][cg=8][pix]
__device__ uint4 g_xpad8[NB * 8 * PHW2];

template <int K> __device__ __forceinline__ float* off_buf() {
    if constexpr (K == 3) return g_off3;
    else if constexpr (K == 5) return g_off5;
    else return g_off7;
}
template <int K> __device__ __forceinline__ float* mask_buf() {
    if constexpr (K == 3) return g_mask3;
    else if constexpr (K == 5) return g_mask5;
    else return g_mask7;
}
template <int K> __device__ __forceinline__ uint32_t* wt2_buf() {
    if constexpr (K == 3) return g_wt2_3;
    else if constexpr (K == 5) return g_wt2_5;
    else return g_wt2_7;
}
template <int K> __device__ __forceinline__ uint32_t* wa2_buf() {
    if constexpr (K == 3) return g_wa2_3;
    else if constexpr (K == 5) return g_wa2_5;
    else return g_wa2_7;
}

__device__ __forceinline__ uint32_t packh2(float a, float b) {
    __half2 h = __floats2half2_rn(a, b);
    return *reinterpret_cast<uint32_t*>(&h);
}

__device__ __forceinline__ void mma16(float c[4], uint32_t a0, uint32_t a1,
                                      uint32_t a2, uint32_t a3,
                                      uint32_t b0, uint32_t b1) {
    asm volatile(
        "mma.sync.aligned.m16n8k16.row.col.f32.f16.f16.f32 "
        "{%0,%1,%2,%3},{%4,%5,%6,%7},{%8,%9},{%0,%1,%2,%3};"
        : "+f"(c[0]), "+f"(c[1]), "+f"(c[2]), "+f"(c[3])
        : "r"(a0), "r"(a1), "r"(a2), "r"(a3), "r"(b0), "r"(b1));
}

// slot within a k16 block for local k-pair j (0..7): frag wants kp=tg at 2tg,
// kp=tg+4 at 2tg+1 so (b0,b1) is one 8-byte load.
__device__ __forceinline__ int slot8(int j) { return (j & 3) * 2 + (j >> 2); }

// ---------------- prep: pack weights + padded image into half2 ---------------
#define S_WT2 (83 * 2048)                 // (9+25+49)*32*64
#define S_WA2 (288 * 32 + 800 * 96 + 1568 * 160)
#define S_XP8 (NB * 8 * PHW2)
__global__ __launch_bounds__(256) void prep_all(
    const float* __restrict__ x,
    const float* __restrict__ wd3, const float* __restrict__ wd5,
    const float* __restrict__ wd7,
    const float* __restrict__ wo3, const float* __restrict__ wm3,
    const float* __restrict__ wo5, const float* __restrict__ wm5,
    const float* __restrict__ wo7, const float* __restrict__ wm7) {
    int idx = blockIdx.x * 256 + threadIdx.x;
    if (idx < S_WT2) {
        const float* w; uint32_t* dst; int kk;
        if (idx < 9 * 2048) { w = wd3; dst = g_wt2_3; kk = 9; }
        else if (idx < 34 * 2048) { idx -= 9 * 2048; w = wd5; dst = g_wt2_5; kk = 25; }
        else { idx -= 34 * 2048; w = wd7; dst = g_wt2_7; kk = 49; }
        int oc = idx & 63;
        int kp = (idx >> 6) & 31;
        int t = idx >> 11;
        int c = kp * 2;
        dst[idx] = packh2(w[(oc * 64 + c) * kk + t], w[(oc * 64 + c + 1) * kk + t]);
        return;
    }
    idx -= S_WT2;
    if (idx < S_WA2) {
        const float* wo; const float* wm; uint32_t* dst; int kk, ocw;
        if (idx < 288 * 32) { wo = wo3; wm = wm3; dst = g_wa2_3; kk = 9; ocw = 32; }
        else if (idx < 288 * 32 + 800 * 96) {
            idx -= 288 * 32; wo = wo5; wm = wm5; dst = g_wa2_5; kk = 25; ocw = 96;
        } else {
            idx -= 288 * 32 + 800 * 96; wo = wo7; wm = wm7; dst = g_wa2_7; kk = 49; ocw = 160;
        }
        int oc = idx % ocw;
        int kpg = idx / ocw;
        int t = kpg >> 5;
        int c = (kpg & 31) * 2;
        float va = 0.f, vb = 0.f;
        if (oc < 2 * kk) {
            va = wo[(oc * 64 + c) * kk + t];
            vb = wo[(oc * 64 + c + 1) * kk + t];
        } else if (oc < 3 * kk) {
            va = wm[((oc - 2 * kk) * 64 + c) * kk + t];
            vb = wm[((oc - 2 * kk) * 64 + c + 1) * kk + t];
        }
        dst[idx] = packh2(va, vb);
        return;
    }
    idx -= S_WA2;
    if (idx < S_XP8) {
        int pix = idx % PHW2;
        int rest = idx / PHW2;
        int cg = rest & 7;
        int b = rest >> 3;
        int yp = pix / PH - 3;
        int xp = pix % PH - 3;
        uint4 v = make_uint4(0u, 0u, 0u, 0u);
        if (yp >= 0 && yp < HH && xp >= 0 && xp < WW) {
            const float* xs = x + (b * 64 + cg * 8) * HWSZ + yp * WW + xp;
            v.x = packh2(__ldg(xs), __ldg(xs + HWSZ));
            v.y = packh2(__ldg(xs + 2 * HWSZ), __ldg(xs + 3 * HWSZ));
            v.z = packh2(__ldg(xs + 4 * HWSZ), __ldg(xs + 5 * HWSZ));
            v.w = packh2(__ldg(xs + 6 * HWSZ), __ldg(xs + 7 * HWSZ));
        }
        g_xpad8[idx] = v;
    }
}

// ---------------- conv phase: G oc-groups x 128 pix per CTA, fp16 MMA --------
// Tap-sized chunks (32 kp = one tap), depth-1 register pipeline; B staged with
// 4x LDG.128 from the 8-channel-interleaved image. (R15, best measured.)
template <int K, int G, int OCW, int OCB>
__device__ __forceinline__ void conv_branch(
    const float* __restrict__ b_off, const float* __restrict__ b_mask,
    uint32_t* smem, int b, int pbase) {
    constexpr int KK = K * K;
    constexpr int P = K / 2;
    constexpr int NCH = KK;              // one chunk per tap
    constexpr int MST = G * 32 + 8;      // u32 stride, mod 32 == 8
    constexpr int BST = 40;              // 32 kp + pad, mod 32 == 8

    uint32_t* As = smem;                 // 2 * 32 * MST
    uint32_t* Bs = smem + 2 * 32 * MST;  // 2 * 128 * BST

    const int tid = threadIdx.x;
    const int wid = tid >> 5;
    const int lane = tid & 31;
    const int g = lane >> 2;
    const int tg = lane & 3;
    const int mbase = (wid & 1) * 16;
    const int nbase = (wid >> 1) * 32;

    // staging ids
    const int akp = tid >> 3;            // A: kp row 0..31
    const int ao4 = (tid & 7) * 4;       // A: 4 u32 (4 oc)
    const int bpix = tid & 127;          // B: pixel
    const int blk = tid >> 7;            // B: channel half (4 cgroups)
    const int phw = pbase + bpix;
    const int ph = phw / WW;
    const int pw = phw - ph * WW;
    const int pbase86 = (ph + 3 - P) * PH + (pw + 3 - P);
    const uint4* xp8blk = g_xpad8 + (b * 8 + blk * 4) * PHW2;
    const uint32_t* wa = wa2_buf<K>();

    uint4 aR[G];
    uint32_t bR[16];

    auto ldgAB = [&](int t) {
#pragma unroll
        for (int gi = 0; gi < G; ++gi)
            aR[gi] = *(const uint4*)(wa + (t * 32 + akp) * OCW + OCB + gi * 32 + ao4);
        const int ky = t / K;
        const int kx = t - ky * K;
        const uint4* src = xp8blk + pbase86 + ky * PH + kx;
#pragma unroll
        for (int c = 0; c < 4; ++c) {
            uint4 v = __ldg(src + c * PHW2);
            bR[c * 4 + 0] = v.x;
            bR[c * 4 + 1] = v.y;
            bR[c * 4 + 2] = v.z;
            bR[c * 4 + 3] = v.w;
        }
    };
    auto stsAB = [&](int buf) {
        uint32_t* Ab = As + buf * 32 * MST;
        uint32_t* Bb = Bs + buf * 128 * BST;
#pragma unroll
        for (int gi = 0; gi < G; ++gi)
            *(uint4*)(Ab + akp * MST + gi * 32 + ao4) = aR[gi];
        uint32_t h[16];
#pragma unroll
        for (int j = 0; j < 16; ++j)
            h[(j >> 3) * 8 + slot8(j & 7)] = bR[j];
        uint32_t* dst = Bb + bpix * BST + blk * 16;
        *(uint4*)(dst) = make_uint4(h[0], h[1], h[2], h[3]);
        *(uint4*)(dst + 4) = make_uint4(h[4], h[5], h[6], h[7]);
        *(uint4*)(dst + 8) = make_uint4(h[8], h[9], h[10], h[11]);
        *(uint4*)(dst + 12) = make_uint4(h[12], h[13], h[14], h[15]);
    };

    float acc[G][4][4];
#pragma unroll
    for (int gi = 0; gi < G; ++gi)
#pragma unroll
        for (int i = 0; i < 4; ++i)
#pragma unroll
            for (int l = 0; l < 4; ++l) acc[gi][i][l] = 0.f;

    ldgAB(0);
    for (int n = 0; n < NCH; ++n) {
        const int buf = n & 1;
        stsAB(buf);
        __syncthreads();
        const uint32_t* Ab = As + buf * 32 * MST;
        const uint32_t* Bb = Bs + buf * 128 * BST;
#pragma unroll
        for (int kb = 0; kb < 4; ++kb) {
            uint2 bb[4];
#pragma unroll
            for (int nt = 0; nt < 4; ++nt)
                bb[nt] = *(const uint2*)(Bb + (nbase + nt * 8 + g) * BST + kb * 8 + 2 * tg);
            const uint32_t* Ar = Ab + (kb * 8 + tg) * MST;
            const uint32_t* Ar4 = Ab + (kb * 8 + tg + 4) * MST;
#pragma unroll
            for (int gi = 0; gi < G; ++gi) {
                const int mb = gi * 32 + mbase + g;
                uint32_t a0 = Ar[mb];
                uint32_t a1 = Ar[mb + 8];
                uint32_t a2 = Ar4[mb];
                uint32_t a3 = Ar4[mb + 8];
#pragma unroll
                for (int nt = 0; nt < 4; ++nt)
                    mma16(acc[gi][nt], a0, a1, a2, a3, bb[nt].x, bb[nt].y);
            }
        }
        if (n + 1 < NCH) ldgAB(n + 1);
    }

    // epilogue
#pragma unroll
    for (int gi = 0; gi < G; ++gi)
#pragma unroll
        for (int r = 0; r < 2; ++r) {
            int ocl = OCB + gi * 32 + mbase + g + r * 8;
            float* dst;
            float bias;
            bool msk;
            if (ocl < 2 * KK) {
                dst = off_buf<K>() + ((size_t)(b * 2 * KK + ocl)) * HWSZ;
                bias = __ldg(b_off + ocl);
                msk = false;
            } else if (ocl < 3 * KK) {
                dst = mask_buf<K>() + ((size_t)(b * KK + (ocl - 2 * KK))) * HWSZ;
                bias = __ldg(b_mask + (ocl - 2 * KK));
                msk = true;
            } else continue;
#pragma unroll
            for (int nt = 0; nt < 4; ++nt) {
                int col = pbase + nbase + nt * 8 + tg * 2;
                float f0 = acc[gi][nt][r * 2] + bias;
                float f1 = acc[gi][nt][r * 2 + 1] + bias;
                if (msk) {
                    f0 = 1.f / (1.f + __expf(-f0));
                    f1 = 1.f / (1.f + __expf(-f1));
                }
                *(float2*)(dst + col) = make_float2(f0, f1);
            }
        }
}

// cid map: 0-99 k7 G=3 | 100-199 k7 G=2 | 200-299 k5 | 300-399 k3
__global__ __launch_bounds__(256, 2) void conv_tc(
    const float* __restrict__ b_off3, const float* __restrict__ b_mask3,
    const float* __restrict__ b_off5, const float* __restrict__ b_mask5,
    const float* __restrict__ b_off7, const float* __restrict__ b_mask7,
    int cidbase) {
    extern __shared__ uint32_t dynsmem_c[];
    const int cid = cidbase + blockIdx.x;
    const int j = cid % 100;
    const int b = j / 50;
    const int pbase = (j % 50) * 128;
    if (cid < 100)
        conv_branch<7, 3, 160, 0>(b_off7, b_mask7, dynsmem_c, b, pbase);
    else if (cid < 200)
        conv_branch<7, 2, 160, 96>(b_off7, b_mask7, dynsmem_c, b, pbase);
    else if (cid < 300)
        conv_branch<5, 3, 96, 0>(b_off5, b_mask5, dynsmem_c, b, pbase);
    else
        conv_branch<3, 1, 32, 0>(b_off3, b_mask3, dynsmem_c, b, pbase);
}

// ---------------- deform phase: 64 oc x 128 pix per CTA, fp16 MMA ------------
// Tap-sized chunks; gather uses 16B corner loads (8 channels each) from the
// interleaved fp16 image; fp32 combine. (R15, best measured.)
template <int K, int BROFF>
__device__ __forceinline__ void deform_branch(
    float* __restrict__ out, uint32_t* smem, int b, int pbase) {
    constexpr int KK = K * K;
    constexpr int P = K / 2;
    constexpr int NCH = KK;              // one chunk per tap
    constexpr int AST = 72;              // u32 stride, mod 32 == 8
    constexpr int BST = 40;              // 32 kp + pad, mod 32 == 8

    uint32_t* As = smem;                 // 2 * 32 * 72
    uint32_t* Bs = smem + 2 * 32 * AST;  // 2 * 128 * 40

    const int tid = threadIdx.x;
    const int wid = tid >> 5;
    const int lane = tid & 31;
    const int g = lane >> 2;
    const int tg = lane & 3;
    const int mbase = (wid & 1) * 32;    // 2 m-groups of 32
    const int nbase = (wid >> 1) * 32;   // 4 n-groups of 32

    // staging ids
    const int pix = tid & 127;
    const int blk = tid >> 7;            // channel half (4 cgroups)
    const int akp = tid >> 4;            // A: kp rows akp and akp+16
    const int ao4 = (tid & 15) * 4;      // A: 4 u32 (4 oc)
    const int shw = pbase + pix;
    const int sh = shw / WW;
    const int swp = shw - sh * WW;
    const uint4* xp8blk = g_xpad8 + (b * 8 + blk * 4) * PHW2;
    const uint32_t* wt = wt2_buf<K>();
    const float* goff = off_buf<K>();
    const float* gmask = mask_buf<K>();

    float r_oy, r_ox, r_m;
    uint4 aR[2];
    uint32_t hR[16];

    auto prefetch_raw = [&](int t) {
        if (t < KK) {
            r_oy = __ldg(goff + (b * 2 * KK + 2 * t) * HWSZ + shw);
            r_ox = __ldg(goff + (b * 2 * KK + 2 * t + 1) * HWSZ + shw);
            r_m = __ldg(gmask + (b * KK + t) * HWSZ + shw);
        }
    };

    auto ldgAB = [&](int t) {
        aR[0] = *(const uint4*)(wt + (t * 32 + akp) * 64 + ao4);
        aR[1] = *(const uint4*)(wt + (t * 32 + akp + 16) * 64 + ao4);
        int ty = t / K, tx = t - ty * K;
        float py = (float)(sh - P + ty + 3) + r_oy;
        float px = (float)(swp - P + tx + 3) + r_ox;
        float y0f = floorf(py), x0f = floorf(px);
        float wy1 = py - y0f, wx1 = px - x0f;
        float wy0 = 1.f - wy1, wx0 = 1.f - wx1;
        int y0 = min(max((int)y0f, 0), PH - 1);
        int y1 = min(max((int)y0f + 1, 0), PH - 1);
        int x0 = min(max((int)x0f, 0), PH - 1);
        int x1 = min(max((int)x0f + 1, 0), PH - 1);
        float4 dw = make_float4(wy0 * wx0 * r_m, wy0 * wx1 * r_m,
                                wy1 * wx0 * r_m, wy1 * wx1 * r_m);
        int4 di = make_int4(y0 * PH + x0, y0 * PH + x1, y1 * PH + x0, y1 * PH + x1);
        prefetch_raw(t + 1);
#pragma unroll
        for (int c = 0; c < 4; ++c) {
            const uint4* gp = xp8blk + c * PHW2;
            uint4 s0 = __ldg(gp + di.x);
            uint4 s1 = __ldg(gp + di.y);
            uint4 s2 = __ldg(gp + di.z);
            uint4 s3 = __ldg(gp + di.w);
            const __half2* h0 = (const __half2*)&s0;
            const __half2* h1 = (const __half2*)&s1;
            const __half2* h2 = (const __half2*)&s2;
            const __half2* h3 = (const __half2*)&s3;
#pragma unroll
            for (int q = 0; q < 4; ++q) {
                float2 f0 = __half22float2(h0[q]);
                float2 f1 = __half22float2(h1[q]);
                float2 f2 = __half22float2(h2[q]);
                float2 f3 = __half22float2(h3[q]);
                float va = dw.x * f0.x + dw.y * f1.x + dw.z * f2.x + dw.w * f3.x;
                float vb = dw.x * f0.y + dw.y * f1.y + dw.z * f2.y + dw.w * f3.y;
                hR[c * 4 + q] = packh2(va, vb);
            }
        }
    };
    auto stsAB = [&](int buf) {
        uint32_t* Ab = As + buf * 32 * AST;
        uint32_t* Bb = Bs + buf * 128 * BST;
        *(uint4*)(Ab + akp * AST + ao4) = aR[0];
        *(uint4*)(Ab + (akp + 16) * AST + ao4) = aR[1];
        uint32_t h[16];
#pragma unroll
        for (int i = 0; i < 16; ++i)
            h[(i >> 3) * 8 + slot8(i & 7)] = hR[i];
        uint32_t* dst = Bb + pix * BST + blk * 16;
        *(uint4*)(dst) = make_uint4(h[0], h[1], h[2], h[3]);
        *(uint4*)(dst + 4) = make_uint4(h[4], h[5], h[6], h[7]);
        *(uint4*)(dst + 8) = make_uint4(h[8], h[9], h[10], h[11]);
        *(uint4*)(dst + 12) = make_uint4(h[12], h[13], h[14], h[15]);
    };

    float acc[2][4][4];
#pragma unroll
    for (int mt = 0; mt < 2; ++mt)
#pragma unroll
        for (int i = 0; i < 4; ++i)
#pragma unroll
            for (int l = 0; l < 4; ++l) acc[mt][i][l] = 0.f;

    prefetch_raw(0);
    ldgAB(0);
    for (int n = 0; n < NCH; ++n) {
        const int buf = n & 1;
        stsAB(buf);
        __syncthreads();
        const uint32_t* Ab = As + buf * 32 * AST;
        const uint32_t* Bb = Bs + buf * 128 * BST;
#pragma unroll
        for (int kb = 0; kb < 4; ++kb) {
            uint2 bb[4];
#pragma unroll
            for (int nt = 0; nt < 4; ++nt)
                bb[nt] = *(const uint2*)(Bb + (nbase + nt * 8 + g) * BST + kb * 8 + 2 * tg);
            const uint32_t* Ar = Ab + (kb * 8 + tg) * AST;
            const uint32_t* Ar4 = Ab + (kb * 8 + tg + 4) * AST;
#pragma unroll
            for (int mt = 0; mt < 2; ++mt) {
                const int mb = mbase + mt * 16 + g;
                uint32_t a0 = Ar[mb];
                uint32_t a1 = Ar[mb + 8];
                uint32_t a2 = Ar4[mb];
                uint32_t a3 = Ar4[mb + 8];
#pragma unroll
                for (int nt = 0; nt < 4; ++nt)
                    mma16(acc[mt][nt], a0, a1, a2, a3, bb[nt].x, bb[nt].y);
            }
        }
        if (n + 1 < NCH) ldgAB(n + 1);
    }

#pragma unroll
    for (int mt = 0; mt < 2; ++mt)
#pragma unroll
        for (int r = 0; r < 2; ++r) {
            int ocl = BROFF + mbase + mt * 16 + g + r * 8;
            float* dst = out + ((size_t)(b * 192 + ocl)) * HWSZ;
#pragma unroll
            for (int nt = 0; nt < 4; ++nt) {
                int col = pbase + nbase + nt * 8 + tg * 2;
                *(float2*)(dst + col) =
                    make_float2(acc[mt][nt][r * 2], acc[mt][nt][r * 2 + 1]);
            }
        }
}

// cid map: 0-99 k7 | 100-199 k5 | 200-299 k3
__global__ __launch_bounds__(256, 2) void deform_tc(float* __restrict__ out,
                                                    int cidbase) {
    extern __shared__ uint32_t dynsmem_d[];
    const int cid = cidbase + blockIdx.x;
    const int j = cid % 100;
    const int b = j / 50;
    const int pbase = (j % 50) * 128;
    if (cid < 100) deform_branch<7, 128>(out, dynsmem_d, b, pbase);
    else if (cid < 200) deform_branch<5, 64>(out, dynsmem_d, b, pbase);
    else deform_branch<3, 0>(out, dynsmem_d, b, pbase);
}

extern "C" void kernel_launch(void* const* d_in, const int* in_sizes, int n_in,
                              void* d_out, int out_size) {
    (void)in_sizes; (void)n_in; (void)out_size;
    const float* x       = (const float*)d_in[0];
    const float* w_off3  = (const float*)d_in[1];
    const float* b_off3  = (const float*)d_in[2];
    const float* w_mask3 = (const float*)d_in[3];
    const float* b_mask3 = (const float*)d_in[4];
    const float* w_dcn3  = (const float*)d_in[5];
    const float* w_off5  = (const float*)d_in[6];
    const float* b_off5  = (const float*)d_in[7];
    const float* w_mask5 = (const float*)d_in[8];
    const float* b_mask5 = (const float*)d_in[9];
    const float* w_dcn5  = (const float*)d_in[10];
    const float* w_off7  = (const float*)d_in[11];
    const float* b_off7  = (const float*)d_in[12];
    const float* w_mask7 = (const float*)d_in[13];
    const float* b_mask7 = (const float*)d_in[14];
    const float* w_dcn7  = (const float*)d_in[15];
    float* out = (float*)d_out;

    const int conv_smem = (2 * 32 * 104 + 2 * 128 * 40) * 4;
    const int def_smem = (2 * 32 * 72 + 2 * 128 * 40) * 4;
    cudaFuncSetAttribute(conv_tc, cudaFuncAttributeMaxDynamicSharedMemorySize,
                         conv_smem);
    cudaFuncSetAttribute(deform_tc, cudaFuncAttributeMaxDynamicSharedMemorySize,
                         def_smem);

    // forked-stream two-pipeline schedule (capture-legal fork/join):
    //   A (launch stream): conv(k7) -> deform(k7)
    //   B (s2):            conv(k5,k3) -> deform(k5,k3)
    cudaStream_t s2;
    cudaStreamCreateWithFlags(&s2, cudaStreamNonBlocking);
    cudaEvent_t eFork, eJoin;
    cudaEventCreateWithFlags(&eFork, cudaEventDisableTiming);
    cudaEventCreateWithFlags(&eJoin, cudaEventDisableTiming);

    const int prep_total = S_WT2 + S_WA2 + S_XP8;
    prep_all<<<(prep_total + 255) / 256, 256>>>(
        x, w_dcn3, w_dcn5, w_dcn7,
        w_off3, w_mask3, w_off5, w_mask5, w_off7, w_mask7);
    cudaEventRecord(eFork, 0);
    cudaStreamWaitEvent(s2, eFork, 0);

    // pipeline A: k7
    conv_tc<<<200, 256, conv_smem, 0>>>(
        b_off3, b_mask3, b_off5, b_mask5, b_off7, b_mask7, 0);
    deform_tc<<<100, 256, def_smem, 0>>>(out, 0);

    // pipeline B: k5 + k3
    conv_tc<<<200, 256, conv_smem, s2>>>(
        b_off3, b_mask3, b_off5, b_mask5, b_off7, b_mask7, 200);
    deform_tc<<<200, 256, def_smem, s2>>>(out, 100);
    cudaEventRecord(eJoin, s2);
    cudaStreamWaitEvent(0, eJoin, 0);
    // streams/events intentionally not destroyed mid-capture (leaked per call;
    // kernel_launch is invoked only a handful of times).
}